// round 10
// baseline (speedup 1.0000x reference)
#include <cuda_runtime.h>
#include <cuda_bf16.h>
#include <cuda_fp16.h>
#include <cstdint>

#define NB   4
#define CC   128
#define CR   64
#define HWS  4096
#define NJ   64            // j-tiles of 64
#define STAGE_BYTES 32768  // Kh 8K + Kl 8K + Vh 16K
#define NSTAGE 3

// ---------------------------------------------------------------------------
// Scratch
// ---------------------------------------------------------------------------
__device__ __nv_bfloat16 g_qh[NB * HWS * CR];
__device__ __nv_bfloat16 g_ql[NB * HWS * CR];
__device__ __nv_bfloat16 g_kh[NB * HWS * CR];
__device__ __nv_bfloat16 g_kl[NB * HWS * CR];
__device__ __half        g_vh[NB * HWS * CC];

// ---------------------------------------------------------------------------
// helpers
// ---------------------------------------------------------------------------
__device__ __forceinline__ uint32_t smem_u32(const void* p) {
    uint32_t a;
    asm("{ .reg .u64 t; cvta.to.shared.u64 t, %1; cvt.u32.u64 %0, t; }" : "=r"(a) : "l"(p));
    return a;
}
__device__ __forceinline__ uint32_t packbf(float a, float b) {
    __nv_bfloat162 t = __floats2bfloat162_rn(a, b);
    return *reinterpret_cast<uint32_t*>(&t);
}
__device__ __forceinline__ uint32_t packh(float a, float b) {
    __half2 t = __floats2half2_rn(a, b);
    return *reinterpret_cast<uint32_t*>(&t);
}
__device__ __forceinline__ uint32_t ld32(const void* p) {
    return *reinterpret_cast<const uint32_t*>(p);
}
__device__ __forceinline__ void cpasync16(uint32_t dst, const void* src) {
    asm volatile("cp.async.cg.shared.global [%0], [%1], 16;" :: "r"(dst), "l"(src));
}

// mbarrier ops
#define MBAR_INIT(mb, c) asm volatile("mbarrier.init.shared.b64 [%0], %1;" :: "r"(mb), "r"(c) : "memory")
#define MBAR_ARRIVE(mb)  asm volatile("mbarrier.arrive.shared.b64 _, [%0];" :: "r"(mb) : "memory")
#define CPA_ARRIVE(mb)   asm volatile("cp.async.mbarrier.arrive.noinc.shared.b64 [%0];" :: "r"(mb) : "memory")

#define MBAR_WAIT(mb, ph) do {                                                   \
    uint32_t _m = (mb), _p = (uint32_t)(ph), _d;                                 \
    asm volatile("{ .reg .pred p; mbarrier.try_wait.parity.acquire.cta.shared::cta.b64 p, [%1], %2; selp.b32 %0,1,0,p; }" \
                 : "=r"(_d) : "r"(_m), "r"(_p) : "memory");                      \
    if (!_d) {                                                                   \
        asm volatile("{ .reg .pred P1; WL%=: mbarrier.try_wait.parity.acquire.cta.shared::cta.b64 P1, [%0], %1, 0x989680; @P1 bra.uni WD%=; bra.uni WL%=; WD%=: }" \
                     :: "r"(_m), "r"(_p) : "memory");                            \
    }                                                                            \
} while (0)

__device__ __forceinline__ void ldsm4(uint32_t& a, uint32_t& b, uint32_t& c, uint32_t& d, uint32_t addr) {
    asm volatile("ldmatrix.sync.aligned.m8n8.x4.shared.b16 {%0,%1,%2,%3}, [%4];"
                 : "=r"(a), "=r"(b), "=r"(c), "=r"(d) : "r"(addr));
}
__device__ __forceinline__ void ldsm4t(uint32_t& a, uint32_t& b, uint32_t& c, uint32_t& d, uint32_t addr) {
    asm volatile("ldmatrix.sync.aligned.m8n8.x4.trans.shared.b16 {%0,%1,%2,%3}, [%4];"
                 : "=r"(a), "=r"(b), "=r"(c), "=r"(d) : "r"(addr));
}
__device__ __forceinline__ void mma_bf16(float* c, const uint32_t* a, uint32_t b0, uint32_t b1) {
    asm volatile("mma.sync.aligned.m16n8k16.row.col.f32.bf16.bf16.f32 "
                 "{%0,%1,%2,%3}, {%4,%5,%6,%7}, {%8,%9}, {%0,%1,%2,%3};"
                 : "+f"(c[0]), "+f"(c[1]), "+f"(c[2]), "+f"(c[3])
                 : "r"(a[0]), "r"(a[1]), "r"(a[2]), "r"(a[3]), "r"(b0), "r"(b1));
}
__device__ __forceinline__ void mma_f16(float* c, const uint32_t* a, uint32_t b0, uint32_t b1) {
    asm volatile("mma.sync.aligned.m16n8k16.row.col.f32.f16.f16.f32 "
                 "{%0,%1,%2,%3}, {%4,%5,%6,%7}, {%8,%9}, {%0,%1,%2,%3};"
                 : "+f"(c[0]), "+f"(c[1]), "+f"(c[2]), "+f"(c[3])
                 : "r"(a[0]), "r"(a[1]), "r"(a[2]), "r"(a[3]), "r"(b0), "r"(b1));
}

// ---------------------------------------------------------------------------
// Kernel 1: 1x1 convs + PReLU -> split precision scratch (unchanged)
// ---------------------------------------------------------------------------
__global__ __launch_bounds__(256) void proj_kernel(
    const float* __restrict__ x,
    const float* __restrict__ w1, const float* __restrict__ b1, const float* __restrict__ a1,
    const float* __restrict__ w2, const float* __restrict__ b2, const float* __restrict__ a2,
    const float* __restrict__ wa, const float* __restrict__ ba, const float* __restrict__ aa)
{
    __shared__ float sw[16][68];
    __shared__ float sx[16][68];

    const int n  = blockIdx.z;
    const int o0 = blockIdx.y * 64;
    const int j0 = blockIdx.x * 64;
    const int tid = threadIdx.x;
    const int tx = tid & 15;       // position dir
    const int ty = tid >> 4;       // channel dir

    const float* W; const float* bias; const float* aptr; int oseg;
    if (o0 < 64)        { W = w1; bias = b1; aptr = a1; oseg = o0;       }
    else if (o0 < 128)  { W = w2; bias = b2; aptr = a2; oseg = o0 - 64;  }
    else                { W = wa; bias = ba; aptr = aa; oseg = o0 - 128; }
    const float alpha = *aptr;

    float acc[4][4];
#pragma unroll
    for (int oi = 0; oi < 4; ++oi)
#pragma unroll
        for (int jj = 0; jj < 4; ++jj) acc[oi][jj] = 0.f;

    for (int k0 = 0; k0 < CC; k0 += 16) {
        for (int idx = tid; idx < 16 * 64; idx += 256) {
            const int c_l = idx & 15, o_l = idx >> 4;
            sw[c_l][o_l] = W[(oseg + o_l) * CC + k0 + c_l];
        }
        for (int idx = tid; idx < 16 * 64; idx += 256) {
            const int c_l = idx >> 6, j_l = idx & 63;
            sx[c_l][j_l] = x[(n * CC + k0 + c_l) * HWS + j0 + j_l];
        }
        __syncthreads();
#pragma unroll
        for (int kk = 0; kk < 16; ++kk) {
            const float4 wv = *reinterpret_cast<const float4*>(&sw[kk][ty * 4]);
            const float4 xv = *reinterpret_cast<const float4*>(&sx[kk][tx * 4]);
            const float wr[4] = {wv.x, wv.y, wv.z, wv.w};
            const float xr[4] = {xv.x, xv.y, xv.z, xv.w};
#pragma unroll
            for (int oi = 0; oi < 4; ++oi)
#pragma unroll
                for (int jj = 0; jj < 4; ++jj)
                    acc[oi][jj] = fmaf(wr[oi], xr[jj], acc[oi][jj]);
        }
        __syncthreads();
    }

#pragma unroll
    for (int oi = 0; oi < 4; ++oi) {
        const float bv = bias[oseg + ty * 4 + oi];
#pragma unroll
        for (int jj = 0; jj < 4; ++jj) {
            const float v = acc[oi][jj] + bv;
            acc[oi][jj] = (v >= 0.f) ? v : alpha * v;
        }
    }

    if (o0 < 128) {
        __nv_bfloat16* dh = (o0 < 64) ? g_qh : g_kh;
        __nv_bfloat16* dl = (o0 < 64) ? g_ql : g_kl;
#pragma unroll
        for (int jj = 0; jj < 4; ++jj) {
            const int pos = j0 + tx * 4 + jj;
            float h[4], l[4];
#pragma unroll
            for (int oi = 0; oi < 4; ++oi) {
                const float v = acc[oi][jj];
                const float hf = __bfloat162float(__float2bfloat16_rn(v));
                h[oi] = hf;
                l[oi] = v - hf;
            }
            const size_t off = ((size_t)(n * HWS + pos)) * CR + ty * 4;
            uint2 hv = make_uint2(packbf(h[0], h[1]), packbf(h[2], h[3]));
            uint2 lv = make_uint2(packbf(l[0], l[1]), packbf(l[2], l[3]));
            *reinterpret_cast<uint2*>(&dh[off]) = hv;
            *reinterpret_cast<uint2*>(&dl[off]) = lv;
        }
    } else {
#pragma unroll
        for (int jj = 0; jj < 4; ++jj) {
            const int pos = j0 + tx * 4 + jj;
            const size_t off = ((size_t)(n * HWS + pos)) * CC + oseg + ty * 4;
            uint2 hv = make_uint2(packh(acc[0][jj], acc[1][jj]),
                                  packh(acc[2][jj], acc[3][jj]));
            *reinterpret_cast<uint2*>(&g_vh[off]) = hv;
        }
    }
}

// ---------------------------------------------------------------------------
// stage loader (128 threads): K hi/lo (8K each) + V (16K), XOR-swizzled
// ---------------------------------------------------------------------------
__device__ __forceinline__ void load_tile(uint32_t stage, int n, int jt, int tid) {
    const char* kh = reinterpret_cast<const char*>(g_kh) + ((size_t)(n * HWS + jt * 64)) * CR * 2;
    const char* kl = reinterpret_cast<const char*>(g_kl) + ((size_t)(n * HWS + jt * 64)) * CR * 2;
    const char* vh = reinterpret_cast<const char*>(g_vh) + ((size_t)(n * HWS + jt * 64)) * CC * 2;
#pragma unroll
    for (int r = 0; r < 4; ++r) {
        const int idx = tid + 128 * r;            // 0..511
        const int j = idx >> 3, g = idx & 7;
        const int dstoff = j * 128 + (((g ^ (j & 7))) << 4);
        cpasync16(stage + dstoff,         kh + j * 128 + g * 16);
        cpasync16(stage + 8192 + dstoff,  kl + j * 128 + g * 16);
    }
#pragma unroll
    for (int r = 0; r < 8; ++r) {
        const int idx = tid + 128 * r;            // 0..1023
        const int j = idx >> 4, g = idx & 15;
        const int dstoff = j * 256 + (((g ^ (j & 7))) << 4);
        cpasync16(stage + 16384 + dstoff, vh + j * 256 + g * 16);
    }
}

// ---------------------------------------------------------------------------
// Kernel 2: flash attention, 128 thr / 4 warps, i-tile 64, j-tile 64,
// 2 CTAs per SM (independent phase streams), 3-stage mbarrier pipeline.
// ---------------------------------------------------------------------------
__global__ __launch_bounds__(128, 2) void attn_hmma(float* __restrict__ out)
{
    extern __shared__ char smem[];
    const uint32_t sb  = smem_u32(smem);
    const uint32_t BAR = sb + NSTAGE * STAGE_BYTES;   // 6 mbarriers

    const int n   = blockIdx.y;
    const int i0  = blockIdx.x * 64;
    const int tid = threadIdx.x;
    const int w = tid >> 5, lane = tid & 31;
    const int g = lane >> 2, tig = lane & 3;
    const int r1 = w * 16 + g, r2 = r1 + 8;

    if (tid == 0) {
#pragma unroll
        for (int s = 0; s < NSTAGE; ++s) {
            MBAR_INIT(BAR + s * 8, 128);              // full[s]
            MBAR_INIT(BAR + 24 + s * 8, 128);         // empty[s]
        }
    }
    __syncthreads();

    // ---- Q fragments (persistent) ----
    uint32_t qh[4][4], ql[4][4];
    {
        const __nv_bfloat16* q1h = g_qh + ((size_t)(n * HWS + i0 + r1)) * CR + tig * 2;
        const __nv_bfloat16* q2h = g_qh + ((size_t)(n * HWS + i0 + r2)) * CR + tig * 2;
        const __nv_bfloat16* q1l = g_ql + ((size_t)(n * HWS + i0 + r1)) * CR + tig * 2;
        const __nv_bfloat16* q2l = g_ql + ((size_t)(n * HWS + i0 + r2)) * CR + tig * 2;
#pragma unroll
        for (int ks = 0; ks < 4; ++ks) {
            qh[ks][0] = ld32(q1h + ks * 16);     qh[ks][1] = ld32(q2h + ks * 16);
            qh[ks][2] = ld32(q1h + ks * 16 + 8); qh[ks][3] = ld32(q2h + ks * 16 + 8);
            ql[ks][0] = ld32(q1l + ks * 16);     ql[ks][1] = ld32(q2l + ks * 16);
            ql[ks][2] = ld32(q1l + ks * 16 + 8); ql[ks][3] = ld32(q2l + ks * 16 + 8);
        }
    }

    float m1 = -1e30f, m2 = -1e30f, l1 = 0.f, l2 = 0.f;

    float o[16][4];
#pragma unroll
    for (int cn = 0; cn < 16; ++cn)
#pragma unroll
        for (int q = 0; q < 4; ++q) o[cn][q] = 0.f;

    // prologue: stages 0 and 1
    load_tile(sb,               n, 0, tid);  CPA_ARRIVE(BAR);
    load_tile(sb + STAGE_BYTES, n, 1, tid);  CPA_ARRIVE(BAR + 8);

    int sc_ = 0, fpar = 0, fcnt = 0;     // consumer stage + full parity
    int sp_ = 2, epar = 0, ecnt = 0;     // producer stage + empty parity

    for (int jt = 0; jt < NJ; ++jt) {
        const int jt2 = jt + 2;
        if (jt2 < NJ) {
            if (jt2 >= NSTAGE) {
                MBAR_WAIT(BAR + 24 + sp_ * 8, epar);
                if (++ecnt == NSTAGE) { ecnt = 0; epar ^= 1; }
            }
            load_tile(sb + sp_ * STAGE_BYTES, n, jt2, tid);
            CPA_ARRIVE(BAR + sp_ * 8);
            if (++sp_ == NSTAGE) sp_ = 0;
        }

        MBAR_WAIT(BAR + sc_ * 8, fpar);
        if (++fcnt == NSTAGE) { fcnt = 0; fpar ^= 1; }

        const uint32_t KHs = sb + sc_ * STAGE_BYTES;
        const uint32_t VHs = KHs + 16384;

        // ---- QK: S = Qh*Kh + Qh*Kl + Ql*Kh (bf16 3-pass), j-tile 64 ----
        float s[8][4];
#pragma unroll
        for (int jn = 0; jn < 8; ++jn)
#pragma unroll
            for (int q = 0; q < 4; ++q) s[jn][q] = 0.f;

#pragma unroll
        for (int ks = 0; ks < 4; ++ks) {
#pragma unroll
            for (int jnp = 0; jnp < 4; ++jnp) {
                const int j = jnp * 16 + ((lane >> 4) & 1) * 8 + (lane & 7);
                const int gr = ks * 2 + ((lane >> 3) & 1);
                const uint32_t ad = KHs + j * 128 + (((gr) ^ (j & 7)) << 4);
                uint32_t b0, b1, b2, b3;
                ldsm4(b0, b1, b2, b3, ad);
                mma_bf16(s[2 * jnp],     qh[ks], b0, b1);
                mma_bf16(s[2 * jnp + 1], qh[ks], b2, b3);
                mma_bf16(s[2 * jnp],     ql[ks], b0, b1);
                mma_bf16(s[2 * jnp + 1], ql[ks], b2, b3);
                uint32_t c0, c1, c2, c3;
                ldsm4(c0, c1, c2, c3, ad + 8192);
                mma_bf16(s[2 * jnp],     qh[ks], c0, c1);
                mma_bf16(s[2 * jnp + 1], qh[ks], c2, c3);
            }
        }

        // ---- online softmax: true row max (quad-reduced), rescale O ----
        float mx1 = -1e30f, mx2 = -1e30f;
#pragma unroll
        for (int jn = 0; jn < 8; ++jn) {
            mx1 = fmaxf(mx1, fmaxf(s[jn][0], s[jn][1]));
            mx2 = fmaxf(mx2, fmaxf(s[jn][2], s[jn][3]));
        }
        mx1 = fmaxf(mx1, __shfl_xor_sync(0xffffffffu, mx1, 1));
        mx1 = fmaxf(mx1, __shfl_xor_sync(0xffffffffu, mx1, 2));
        mx2 = fmaxf(mx2, __shfl_xor_sync(0xffffffffu, mx2, 1));
        mx2 = fmaxf(mx2, __shfl_xor_sync(0xffffffffu, mx2, 2));
        const float mn1 = fmaxf(m1, mx1), mn2 = fmaxf(m2, mx2);
        const float sc1 = __expf(m1 - mn1), sc2 = __expf(m2 - mn2);
        m1 = mn1; m2 = mn2;
        l1 *= sc1; l2 *= sc2;
#pragma unroll
        for (int cn = 0; cn < 16; ++cn) {
            o[cn][0] *= sc1; o[cn][1] *= sc1;
            o[cn][2] *= sc2; o[cn][3] *= sc2;
        }

        uint32_t ph[8][2];
#pragma unroll
        for (int jn = 0; jn < 8; ++jn) {
            const float p0 = __expf(s[jn][0] - mn1);
            const float p1 = __expf(s[jn][1] - mn1);
            const float p2 = __expf(s[jn][2] - mn2);
            const float p3 = __expf(s[jn][3] - mn2);
            l1 += p0 + p1;
            l2 += p2 + p3;
            ph[jn][0] = packh(p0, p1);
            ph[jn][1] = packh(p2, p3);
        }

        // ---- PV: O += P*V (single fp16 pass) ----
#pragma unroll
        for (int t = 0; t < 4; ++t) {
            const uint32_t a[4] = {ph[2 * t][0], ph[2 * t][1], ph[2 * t + 1][0], ph[2 * t + 1][1]};
#pragma unroll
            for (int cnp = 0; cnp < 8; ++cnp) {
                const int j = t * 16 + ((lane >> 3) & 1) * 8 + (lane & 7);
                const int gr = cnp * 2 + ((lane >> 4) & 1);
                const uint32_t ad = VHs + j * 256 + (((gr) ^ (j & 7)) << 4);
                uint32_t b0, b1, b2, b3;
                ldsm4t(b0, b1, b2, b3, ad);
                mma_f16(o[2 * cnp],     a, b0, b1);
                mma_f16(o[2 * cnp + 1], a, b2, b3);
            }
        }

        MBAR_ARRIVE(BAR + 24 + sc_ * 8);
        if (++sc_ == NSTAGE) sc_ = 0;
    }

    __syncthreads();   // all warps done before tr reuses stage 0

    // ---- epilogue: reduce l over quad, normalize, transpose, store ----
    l1 += __shfl_xor_sync(0xffffffffu, l1, 1);
    l1 += __shfl_xor_sync(0xffffffffu, l1, 2);
    l2 += __shfl_xor_sync(0xffffffffu, l2, 1);
    l2 += __shfl_xor_sync(0xffffffffu, l2, 2);
    const float inv1 = 1.f / l1;
    const float inv2 = 1.f / l2;

    float* tr = reinterpret_cast<float*>(smem);    // [c][i] 32KB
#pragma unroll
    for (int cn = 0; cn < 16; ++cn) {
        const int c = cn * 8 + tig * 2;
        tr[c * 64 + r1]       = o[cn][0] * inv1;
        tr[(c + 1) * 64 + r1] = o[cn][1] * inv1;
        tr[c * 64 + r2]       = o[cn][2] * inv2;
        tr[(c + 1) * 64 + r2] = o[cn][3] * inv2;
    }
    __syncthreads();

#pragma unroll
    for (int rep = 0; rep < 16; ++rep) {
        const int lin = rep * 128 + tid;           // float4 index, 0..2047
        const int c = lin >> 4, i4 = (lin & 15) * 4;
        const float4 f = *reinterpret_cast<const float4*>(&tr[c * 64 + i4]);
        *reinterpret_cast<float4*>(&out[((size_t)n * CC + c) * HWS + i0 + i4]) = f;
    }
}

// ---------------------------------------------------------------------------
extern "C" void kernel_launch(void* const* d_in, const int* in_sizes, int n_in,
                              void* d_out, int out_size)
{
    (void)in_sizes; (void)n_in; (void)out_size;
    const float* x  = (const float*)d_in[0];
    const float* w1 = (const float*)d_in[1];
    const float* b1 = (const float*)d_in[2];
    const float* a1 = (const float*)d_in[3];
    const float* w2 = (const float*)d_in[4];
    const float* b2 = (const float*)d_in[5];
    const float* a2 = (const float*)d_in[6];
    const float* wa = (const float*)d_in[7];
    const float* ba = (const float*)d_in[8];
    const float* aa = (const float*)d_in[9];
    float* out = (float*)d_out;

    proj_kernel<<<dim3(HWS / 64, 4, NB), 256>>>(x, w1, b1, a1, w2, b2, a2, wa, ba, aa);

    const int smem2 = NSTAGE * STAGE_BYTES + 64;   // 96 KB + barriers per CTA
    cudaFuncSetAttribute(attn_hmma, cudaFuncAttributeMaxDynamicSharedMemorySize, smem2);
    attn_hmma<<<dim3(HWS / 64, NB), 128, smem2>>>(out);
}

// round 11
// speedup vs baseline: 1.1825x; 1.1825x over previous
#include <cuda_runtime.h>
#include <cuda_bf16.h>
#include <cuda_fp16.h>
#include <cstdint>

#define NB   4
#define CC   128
#define CR   64
#define HWS  4096
#define NJ   32            // j-tiles of 128
#define STAGE_BYTES 49152  // Kh 16K + Vh 32K
#define NSTAGE 3

// ---------------------------------------------------------------------------
// Scratch
// ---------------------------------------------------------------------------
__device__ __half g_qh[NB * HWS * CR];
__device__ __half g_ql[NB * HWS * CR];
__device__ __half g_kh[NB * HWS * CR];
__device__ __half g_vh[NB * HWS * CC];

// ---------------------------------------------------------------------------
// helpers
// ---------------------------------------------------------------------------
__device__ __forceinline__ uint32_t smem_u32(const void* p) {
    uint32_t a;
    asm("{ .reg .u64 t; cvta.to.shared.u64 t, %1; cvt.u32.u64 %0, t; }" : "=r"(a) : "l"(p));
    return a;
}
__device__ __forceinline__ uint32_t packh(float a, float b) {
    __half2 t = __floats2half2_rn(a, b);
    return *reinterpret_cast<uint32_t*>(&t);
}
__device__ __forceinline__ uint32_t ld32(const void* p) {
    return *reinterpret_cast<const uint32_t*>(p);
}
__device__ __forceinline__ void cpasync16(uint32_t dst, const void* src) {
    asm volatile("cp.async.cg.shared.global [%0], [%1], 16;" :: "r"(dst), "l"(src));
}

// mbarrier ops
#define MBAR_INIT(mb, c) asm volatile("mbarrier.init.shared.b64 [%0], %1;" :: "r"(mb), "r"(c) : "memory")
#define MBAR_ARRIVE(mb)  asm volatile("mbarrier.arrive.shared.b64 _, [%0];" :: "r"(mb) : "memory")
#define CPA_ARRIVE(mb)   asm volatile("cp.async.mbarrier.arrive.noinc.shared.b64 [%0];" :: "r"(mb) : "memory")

#define MBAR_WAIT(mb, ph) do {                                                   \
    uint32_t _m = (mb), _p = (uint32_t)(ph), _d;                                 \
    asm volatile("{ .reg .pred p; mbarrier.try_wait.parity.acquire.cta.shared::cta.b64 p, [%1], %2; selp.b32 %0,1,0,p; }" \
                 : "=r"(_d) : "r"(_m), "r"(_p) : "memory");                      \
    if (!_d) {                                                                   \
        asm volatile("{ .reg .pred P1; WL%=: mbarrier.try_wait.parity.acquire.cta.shared::cta.b64 P1, [%0], %1, 0x989680; @P1 bra.uni WD%=; bra.uni WL%=; WD%=: }" \
                     :: "r"(_m), "r"(_p) : "memory");                            \
    }                                                                            \
} while (0)

__device__ __forceinline__ void ldsm4(uint32_t& a, uint32_t& b, uint32_t& c, uint32_t& d, uint32_t addr) {
    asm volatile("ldmatrix.sync.aligned.m8n8.x4.shared.b16 {%0,%1,%2,%3}, [%4];"
                 : "=r"(a), "=r"(b), "=r"(c), "=r"(d) : "r"(addr));
}
__device__ __forceinline__ void ldsm4t(uint32_t& a, uint32_t& b, uint32_t& c, uint32_t& d, uint32_t addr) {
    asm volatile("ldmatrix.sync.aligned.m8n8.x4.trans.shared.b16 {%0,%1,%2,%3}, [%4];"
                 : "=r"(a), "=r"(b), "=r"(c), "=r"(d) : "r"(addr));
}
__device__ __forceinline__ void mma_f16(float* c, const uint32_t* a, uint32_t b0, uint32_t b1) {
    asm volatile("mma.sync.aligned.m16n8k16.row.col.f32.f16.f16.f32 "
                 "{%0,%1,%2,%3}, {%4,%5,%6,%7}, {%8,%9}, {%0,%1,%2,%3};"
                 : "+f"(c[0]), "+f"(c[1]), "+f"(c[2]), "+f"(c[3])
                 : "r"(a[0]), "r"(a[1]), "r"(a[2]), "r"(a[3]), "r"(b0), "r"(b1));
}

// ---------------------------------------------------------------------------
// Kernel 1: 1x1 convs + PReLU -> fp16 scratch (Q hi/lo split, K/V single)
// ---------------------------------------------------------------------------
__global__ __launch_bounds__(256) void proj_kernel(
    const float* __restrict__ x,
    const float* __restrict__ w1, const float* __restrict__ b1, const float* __restrict__ a1,
    const float* __restrict__ w2, const float* __restrict__ b2, const float* __restrict__ a2,
    const float* __restrict__ wa, const float* __restrict__ ba, const float* __restrict__ aa)
{
    __shared__ float sw[16][68];
    __shared__ float sx[16][68];

    const int n  = blockIdx.z;
    const int o0 = blockIdx.y * 64;
    const int j0 = blockIdx.x * 64;
    const int tid = threadIdx.x;
    const int tx = tid & 15;       // position dir
    const int ty = tid >> 4;       // channel dir

    const float* W; const float* bias; const float* aptr; int oseg;
    if (o0 < 64)        { W = w1; bias = b1; aptr = a1; oseg = o0;       }
    else if (o0 < 128)  { W = w2; bias = b2; aptr = a2; oseg = o0 - 64;  }
    else                { W = wa; bias = ba; aptr = aa; oseg = o0 - 128; }
    const float alpha = *aptr;

    float acc[4][4];
#pragma unroll
    for (int oi = 0; oi < 4; ++oi)
#pragma unroll
        for (int jj = 0; jj < 4; ++jj) acc[oi][jj] = 0.f;

    for (int k0 = 0; k0 < CC; k0 += 16) {
        for (int idx = tid; idx < 16 * 64; idx += 256) {
            const int c_l = idx & 15, o_l = idx >> 4;
            sw[c_l][o_l] = W[(oseg + o_l) * CC + k0 + c_l];
        }
        for (int idx = tid; idx < 16 * 64; idx += 256) {
            const int c_l = idx >> 6, j_l = idx & 63;
            sx[c_l][j_l] = x[(n * CC + k0 + c_l) * HWS + j0 + j_l];
        }
        __syncthreads();
#pragma unroll
        for (int kk = 0; kk < 16; ++kk) {
            const float4 wv = *reinterpret_cast<const float4*>(&sw[kk][ty * 4]);
            const float4 xv = *reinterpret_cast<const float4*>(&sx[kk][tx * 4]);
            const float wr[4] = {wv.x, wv.y, wv.z, wv.w};
            const float xr[4] = {xv.x, xv.y, xv.z, xv.w};
#pragma unroll
            for (int oi = 0; oi < 4; ++oi)
#pragma unroll
                for (int jj = 0; jj < 4; ++jj)
                    acc[oi][jj] = fmaf(wr[oi], xr[jj], acc[oi][jj]);
        }
        __syncthreads();
    }

#pragma unroll
    for (int oi = 0; oi < 4; ++oi) {
        const float bv = bias[oseg + ty * 4 + oi];
#pragma unroll
        for (int jj = 0; jj < 4; ++jj) {
            const float v = acc[oi][jj] + bv;
            acc[oi][jj] = (v >= 0.f) ? v : alpha * v;
        }
    }

    if (o0 < 64) {
        // e1 -> Q fp16 hi/lo split (A-side of QK is exact)
#pragma unroll
        for (int jj = 0; jj < 4; ++jj) {
            const int pos = j0 + tx * 4 + jj;
            float h[4], l[4];
#pragma unroll
            for (int oi = 0; oi < 4; ++oi) {
                const float v = acc[oi][jj];
                const float hf = __half2float(__float2half_rn(v));
                h[oi] = hf;
                l[oi] = v - hf;
            }
            const size_t off = ((size_t)(n * HWS + pos)) * CR + ty * 4;
            uint2 hv = make_uint2(packh(h[0], h[1]), packh(h[2], h[3]));
            uint2 lv = make_uint2(packh(l[0], l[1]), packh(l[2], l[3]));
            *reinterpret_cast<uint2*>(&g_qh[off]) = hv;
            *reinterpret_cast<uint2*>(&g_ql[off]) = lv;
        }
    } else if (o0 < 128) {
        // e2 -> K single fp16
#pragma unroll
        for (int jj = 0; jj < 4; ++jj) {
            const int pos = j0 + tx * 4 + jj;
            const size_t off = ((size_t)(n * HWS + pos)) * CR + ty * 4;
            uint2 hv = make_uint2(packh(acc[0][jj], acc[1][jj]),
                                  packh(acc[2][jj], acc[3][jj]));
            *reinterpret_cast<uint2*>(&g_kh[off]) = hv;
        }
    } else {
        // asm -> V fp16, layout [n][pos][c]
#pragma unroll
        for (int jj = 0; jj < 4; ++jj) {
            const int pos = j0 + tx * 4 + jj;
            const size_t off = ((size_t)(n * HWS + pos)) * CC + oseg + ty * 4;
            uint2 hv = make_uint2(packh(acc[0][jj], acc[1][jj]),
                                  packh(acc[2][jj], acc[3][jj]));
            *reinterpret_cast<uint2*>(&g_vh[off]) = hv;
        }
    }
}

// ---------------------------------------------------------------------------
// stage loader: Kh (16K) + V (32K) tiles, XOR-swizzled, via cp.async
// ---------------------------------------------------------------------------
__device__ __forceinline__ void load_tile(uint32_t stage, int n, int jt, int tid) {
    const char* kh = reinterpret_cast<const char*>(g_kh) + ((size_t)(n * HWS + jt * 128)) * CR * 2;
    const char* vh = reinterpret_cast<const char*>(g_vh) + ((size_t)(n * HWS + jt * 128)) * CC * 2;
#pragma unroll
    for (int r = 0; r < 4; ++r) {
        const int idx = tid + 256 * r;            // 0..1023
        const int j = idx >> 3, g = idx & 7;
        const int dstoff = j * 128 + (((g ^ (j & 7))) << 4);
        cpasync16(stage + dstoff, kh + j * 128 + g * 16);
    }
#pragma unroll
    for (int r = 0; r < 8; ++r) {
        const int idx = tid + 256 * r;            // 0..2047
        const int j = idx >> 4, g = idx & 15;
        const int dstoff = j * 256 + (((g ^ (j & 7))) << 4);
        cpasync16(stage + 16384 + dstoff, vh + j * 256 + g * 16);
    }
}

// ---------------------------------------------------------------------------
// Kernel 2: flash attention on mma.sync, online softmax, 3-stage mbarrier
// pipeline.  QK: A-side fp16 hi/lo 2-pass (exact Q), K single fp16.
// 256 thr / 8 warps, i-tile 128 (m16/warp), j-tile 128.
// ---------------------------------------------------------------------------
__global__ __launch_bounds__(256, 1) void attn_hmma(float* __restrict__ out)
{
    extern __shared__ char smem[];
    const uint32_t sb  = smem_u32(smem);
    const uint32_t BAR = sb + NSTAGE * STAGE_BYTES;   // 6 mbarriers

    const int n   = blockIdx.y;
    const int i0  = blockIdx.x * 128;
    const int tid = threadIdx.x;
    const int w = tid >> 5, lane = tid & 31;
    const int g = lane >> 2, tig = lane & 3;
    const int r1 = w * 16 + g, r2 = r1 + 8;

    if (tid == 0) {
#pragma unroll
        for (int s = 0; s < NSTAGE; ++s) {
            MBAR_INIT(BAR + s * 8, 256);              // full[s]
            MBAR_INIT(BAR + 24 + s * 8, 256);         // empty[s]
        }
    }
    __syncthreads();

    // ---- Q fragments (persistent, fp16 hi/lo) ----
    uint32_t qh[4][4], ql[4][4];
    {
        const __half* q1h = g_qh + ((size_t)(n * HWS + i0 + r1)) * CR + tig * 2;
        const __half* q2h = g_qh + ((size_t)(n * HWS + i0 + r2)) * CR + tig * 2;
        const __half* q1l = g_ql + ((size_t)(n * HWS + i0 + r1)) * CR + tig * 2;
        const __half* q2l = g_ql + ((size_t)(n * HWS + i0 + r2)) * CR + tig * 2;
#pragma unroll
        for (int ks = 0; ks < 4; ++ks) {
            qh[ks][0] = ld32(q1h + ks * 16);     qh[ks][1] = ld32(q2h + ks * 16);
            qh[ks][2] = ld32(q1h + ks * 16 + 8); qh[ks][3] = ld32(q2h + ks * 16 + 8);
            ql[ks][0] = ld32(q1l + ks * 16);     ql[ks][1] = ld32(q2l + ks * 16);
            ql[ks][2] = ld32(q1l + ks * 16 + 8); ql[ks][3] = ld32(q2l + ks * 16 + 8);
        }
    }

    float m1 = -1e30f, m2 = -1e30f, l1 = 0.f, l2 = 0.f;

    float o[16][4];
#pragma unroll
    for (int cn = 0; cn < 16; ++cn)
#pragma unroll
        for (int q = 0; q < 4; ++q) o[cn][q] = 0.f;

    // prologue: stages 0 and 1
    load_tile(sb,               n, 0, tid);  CPA_ARRIVE(BAR);
    load_tile(sb + STAGE_BYTES, n, 1, tid);  CPA_ARRIVE(BAR + 8);

    int sc_ = 0, fpar = 0, fcnt = 0;     // consumer stage + full parity
    int sp_ = 2, epar = 0, ecnt = 0;     // producer stage + empty parity

    for (int jt = 0; jt < NJ; ++jt) {
        const int jt2 = jt + 2;
        if (jt2 < NJ) {
            if (jt2 >= NSTAGE) {
                MBAR_WAIT(BAR + 24 + sp_ * 8, epar);
                if (++ecnt == NSTAGE) { ecnt = 0; epar ^= 1; }
            }
            load_tile(sb + sp_ * STAGE_BYTES, n, jt2, tid);
            CPA_ARRIVE(BAR + sp_ * 8);
            if (++sp_ == NSTAGE) sp_ = 0;
        }

        MBAR_WAIT(BAR + sc_ * 8, fpar);
        if (++fcnt == NSTAGE) { fcnt = 0; fpar ^= 1; }

        const uint32_t KHs = sb + sc_ * STAGE_BYTES;
        const uint32_t VHs = KHs + 16384;

        // ---- QK: S = (Qh + Ql) * Kh  (fp16 A-split 2-pass, exact in Q) ----
        float s[16][4];
#pragma unroll
        for (int jn = 0; jn < 16; ++jn)
#pragma unroll
            for (int q = 0; q < 4; ++q) s[jn][q] = 0.f;

#pragma unroll
        for (int ks = 0; ks < 4; ++ks) {
#pragma unroll
            for (int jnp = 0; jnp < 8; ++jnp) {
                const int j = jnp * 16 + ((lane >> 4) & 1) * 8 + (lane & 7);
                const int gr = ks * 2 + ((lane >> 3) & 1);
                const uint32_t ad = KHs + j * 128 + (((gr) ^ (j & 7)) << 4);
                uint32_t b0, b1, b2, b3;
                ldsm4(b0, b1, b2, b3, ad);
                mma_f16(s[2 * jnp],     qh[ks], b0, b1);
                mma_f16(s[2 * jnp + 1], qh[ks], b2, b3);
                mma_f16(s[2 * jnp],     ql[ks], b0, b1);
                mma_f16(s[2 * jnp + 1], ql[ks], b2, b3);
            }
        }

        // ---- online softmax: true row max (quad-reduced), rescale O ----
        float mx1 = -1e30f, mx2 = -1e30f;
#pragma unroll
        for (int jn = 0; jn < 16; ++jn) {
            mx1 = fmaxf(mx1, fmaxf(s[jn][0], s[jn][1]));
            mx2 = fmaxf(mx2, fmaxf(s[jn][2], s[jn][3]));
        }
        mx1 = fmaxf(mx1, __shfl_xor_sync(0xffffffffu, mx1, 1));
        mx1 = fmaxf(mx1, __shfl_xor_sync(0xffffffffu, mx1, 2));
        mx2 = fmaxf(mx2, __shfl_xor_sync(0xffffffffu, mx2, 1));
        mx2 = fmaxf(mx2, __shfl_xor_sync(0xffffffffu, mx2, 2));
        const float mn1 = fmaxf(m1, mx1), mn2 = fmaxf(m2, mx2);
        const float sc1 = __expf(m1 - mn1), sc2 = __expf(m2 - mn2);
        m1 = mn1; m2 = mn2;
        l1 *= sc1; l2 *= sc2;
#pragma unroll
        for (int cn = 0; cn < 16; ++cn) {
            o[cn][0] *= sc1; o[cn][1] *= sc1;
            o[cn][2] *= sc2; o[cn][3] *= sc2;
        }

        uint32_t ph[16][2];
#pragma unroll
        for (int jn = 0; jn < 16; ++jn) {
            const float p0 = __expf(s[jn][0] - mn1);
            const float p1 = __expf(s[jn][1] - mn1);
            const float p2 = __expf(s[jn][2] - mn2);
            const float p3 = __expf(s[jn][3] - mn2);
            l1 += p0 + p1;
            l2 += p2 + p3;
            ph[jn][0] = packh(p0, p1);
            ph[jn][1] = packh(p2, p3);
        }

        // ---- PV: O += P*V (single fp16 pass) ----
#pragma unroll
        for (int t = 0; t < 8; ++t) {
            const uint32_t a[4] = {ph[2 * t][0], ph[2 * t][1], ph[2 * t + 1][0], ph[2 * t + 1][1]};
#pragma unroll
            for (int cnp = 0; cnp < 8; ++cnp) {
                const int j = t * 16 + ((lane >> 3) & 1) * 8 + (lane & 7);
                const int gr = cnp * 2 + ((lane >> 4) & 1);
                const uint32_t ad = VHs + j * 256 + (((gr) ^ (j & 7)) << 4);
                uint32_t b0, b1, b2, b3;
                ldsm4t(b0, b1, b2, b3, ad);
                mma_f16(o[2 * cnp],     a, b0, b1);
                mma_f16(o[2 * cnp + 1], a, b2, b3);
            }
        }

        MBAR_ARRIVE(BAR + 24 + sc_ * 8);
        if (++sc_ == NSTAGE) sc_ = 0;
    }

    __syncthreads();   // all warps done before tr reuses stage 0

    // ---- epilogue: reduce l over quad, normalize, transpose, store ----
    l1 += __shfl_xor_sync(0xffffffffu, l1, 1);
    l1 += __shfl_xor_sync(0xffffffffu, l1, 2);
    l2 += __shfl_xor_sync(0xffffffffu, l2, 1);
    l2 += __shfl_xor_sync(0xffffffffu, l2, 2);
    const float inv1 = 1.f / l1;
    const float inv2 = 1.f / l2;

    float* tr = reinterpret_cast<float*>(smem);    // [c][i] 64KB
#pragma unroll
    for (int cn = 0; cn < 16; ++cn) {
        const int c = cn * 8 + tig * 2;
        tr[c * 128 + r1]       = o[cn][0] * inv1;
        tr[(c + 1) * 128 + r1] = o[cn][1] * inv1;
        tr[c * 128 + r2]       = o[cn][2] * inv2;
        tr[(c + 1) * 128 + r2] = o[cn][3] * inv2;
    }
    __syncthreads();

#pragma unroll
    for (int rep = 0; rep < 16; ++rep) {
        const int lin = rep * 256 + tid;
        const int c = lin >> 5, i4 = (lin & 31) * 4;
        const float4 f = *reinterpret_cast<const float4*>(&tr[c * 128 + i4]);
        *reinterpret_cast<float4*>(&out[((size_t)n * CC + c) * HWS + i0 + i4]) = f;
    }
}

// ---------------------------------------------------------------------------
extern "C" void kernel_launch(void* const* d_in, const int* in_sizes, int n_in,
                              void* d_out, int out_size)
{
    (void)in_sizes; (void)n_in; (void)out_size;
    const float* x  = (const float*)d_in[0];
    const float* w1 = (const float*)d_in[1];
    const float* b1 = (const float*)d_in[2];
    const float* a1 = (const float*)d_in[3];
    const float* w2 = (const float*)d_in[4];
    const float* b2 = (const float*)d_in[5];
    const float* a2 = (const float*)d_in[6];
    const float* wa = (const float*)d_in[7];
    const float* ba = (const float*)d_in[8];
    const float* aa = (const float*)d_in[9];
    float* out = (float*)d_out;

    proj_kernel<<<dim3(HWS / 64, 4, NB), 256>>>(x, w1, b1, a1, w2, b2, a2, wa, ba, aa);

    const int smem2 = NSTAGE * STAGE_BYTES + 64;   // 144 KB + barriers
    cudaFuncSetAttribute(attn_hmma, cudaFuncAttributeMaxDynamicSharedMemorySize, smem2);
    attn_hmma<<<dim3(HWS / 128, NB), 256, smem2>>>(out);
}